// round 11
// baseline (speedup 1.0000x reference)
#include <cuda_runtime.h>
#include <math.h>

#define BQ 4
#define DQ 256
#define HWQ 16384
#define NPIX (BQ*HWQ)
#define NRQ 32
#define NSQ 64
#define NEGF (-1e30f)
#define INVTAU 10.0f
#define NPAIR 8
#define RPP 160
#define QPAD 260
#define PPAD 72
#define PAIR_SMEM ((32*QPAD + 256*PPAD)*4)
#define BM 256
#define BN 128
#define BKK 16

static __device__ float g_X[(size_t)NPIX*DQ];
static __device__ float g_w1t[DQ*DQ];
static __device__ float g_w2t[DQ*DQ];
static __device__ float g_sum[DQ], g_sumsq[DQ];
static __device__ unsigned char g_m1[NPIX], g_m0[NPIX], g_mv[NPIX];
static __device__ int g_cnt1[BQ], g_cnt0[BQ];
static __device__ float g_hsum[NPAIR*DQ];
static __device__ int g_anc_idx[NPAIR*NRQ];
static __device__ unsigned char g_anc_val[NPAIR*NRQ];
static __device__ int g_pos_idx[NPAIR*NSQ];
static __device__ unsigned char g_pos_val[NPAIR*NSQ];
static __device__ int g_neg_idx[NPAIR*NSQ];
static __device__ unsigned char g_neg_val[NPAIR*NSQ];
static __device__ float g_q[(size_t)NPAIR*RPP*DQ];
static __device__ float g_blsum;
static __device__ int g_incsum;

// fused: init (blk 0..7), w1/w2 transpose (blk 8..71), masks (blk 72..327)
__global__ void k_pre(const float* __restrict__ w1, const float* __restrict__ w2,
                      const float* __restrict__ po, const float* __restrict__ pa,
                      const float* __restrict__ unc, const int* __restrict__ labels) {
    const int bid = blockIdx.x, tid = threadIdx.x;
    if (bid < 8) {
        int t = bid*256 + tid;
        if (t < DQ) { g_sum[t]=0.f; g_sumsq[t]=0.f; }
        if (t < NPAIR*DQ) g_hsum[t]=0.f;
        if (t < BQ) { g_cnt1[t]=0; g_cnt0[t]=0; }
        if (t == 0) { g_blsum=0.f; g_incsum=0; }
        return;
    }
    if (bid < 72) {
        __shared__ float tA[32][33], tB[32][33];
        int wb = bid - 8;
        int bx = (wb&7)*32, by = (wb>>3)*32;
        int tx = tid&31, ty = tid>>5;
        for (int r = ty; r < 32; r += 8) {
            tA[r][tx] = w1[(by+r)*DQ + bx + tx];
            tB[r][tx] = w2[(by+r)*DQ + bx + tx];
        }
        __syncthreads();
        for (int r = ty; r < 32; r += 8) {
            g_w1t[(bx+r)*DQ + by + tx] = tA[tx][r];
            g_w2t[(bx+r)*DQ + by + tx] = tB[tx][r];
        }
        return;
    }
    int g = (bid-72)*256 + tid;
    int b = g >> 14, hw = g & (HWQ-1);
    const float* pob = po + (size_t)b*2*HWQ;
    const float* pab = pa + (size_t)b*2*HWQ;
    int ao = pob[HWQ+hw] > pob[hw];
    int aa = pab[HWQ+hw] > pab[hw];
    bool valid = (ao==aa) && (unc[g] > 0.5f);
    int lab = labels[g];
    bool m1 = valid && (lab==1), m0 = valid && (lab==0);
    g_m1[g] = m1?1:0; g_m0[g] = m0?1:0;
    g_mv[g] = m1?1:(m0?2:0);
    unsigned b1m = __ballot_sync(0xffffffffu, m1);
    unsigned b0m = __ballot_sync(0xffffffffu, m0);
    if ((tid & 31) == 0) {
        atomicAdd(&g_cnt1[b], __popc(b1m));
        atomicAdd(&g_cnt0[b], __popc(b0m));
    }
}

// X = feat @ w1^T + b1, fused BN stats, masked store. (R8 measured winner)
__global__ void __launch_bounds__(256,1)
k_gemm1(const float* __restrict__ feat, const float* __restrict__ b1) {
    __shared__ __align__(16) float As[2][BKK][BM];
    __shared__ __align__(16) float Bs[2][BKK][BN];
    const int tid = threadIdx.x, tx = tid & 15, ty = tid >> 4;
    const int p0 = blockIdx.x*BM;
    const int bq = p0 >> 14, hw0 = p0 & (HWQ-1);
    const int e0 = blockIdx.y*BN;
    const float* fb = feat + (size_t)bq*DQ*HWQ + hw0;
    unsigned sAb = (unsigned)__cvta_generic_to_shared(&As[0][0][0]);
    unsigned sBb = (unsigned)__cvta_generic_to_shared(&Bs[0][0][0]);

    unsigned long long acc[8][8];
    #pragma unroll
    for (int p=0;p<8;p++)
        #pragma unroll
        for (int j=0;j<8;j++) acc[p][j] = 0ull;

    auto load_tiles = [&](int buf, int k0) {
        #pragma unroll
        for (int l=0;l<4;l++) {
            int idx = tid + l*256, kk = idx>>6, m4 = (idx&63)<<2;
            unsigned d = sAb + (((buf*BKK+kk)*BM + m4)<<2);
            const float* s = fb + (size_t)(k0+kk)*HWQ + m4;
            asm volatile("cp.async.cg.shared.global [%0],[%1],16;\n"::"r"(d),"l"(s));
        }
        #pragma unroll
        for (int l=0;l<2;l++) {
            int idx = tid + l*256, kk = idx>>5, e4 = (idx&31)<<2;
            unsigned d = sBb + (((buf*BKK+kk)*BN + e4)<<2);
            const float* s = g_w1t + (k0+kk)*DQ + e0 + e4;
            asm volatile("cp.async.cg.shared.global [%0],[%1],16;\n"::"r"(d),"l"(s));
        }
        asm volatile("cp.async.commit_group;\n");
    };

    load_tiles(0, 0);
    for (int k0=0; k0<DQ; k0+=BKK) {
        int cur = (k0>>4)&1;
        if (k0+BKK < DQ) {
            load_tiles(cur^1, k0+BKK);
            asm volatile("cp.async.wait_group 1;\n");
        } else {
            asm volatile("cp.async.wait_group 0;\n");
        }
        __syncthreads();
        #pragma unroll
        for (int kk=0;kk<BKK;kk++) {
            unsigned long long ap[8];
            const unsigned long long* ar =
                (const unsigned long long*)&As[cur][kk][ty*16];
            #pragma unroll
            for (int p=0;p<8;p++) ap[p] = ar[p];
            float4 w0 = *(float4*)&Bs[cur][kk][tx*8];
            float4 w1v = *(float4*)&Bs[cur][kk][tx*8+4];
            float wv[8] = {w0.x,w0.y,w0.z,w0.w,w1v.x,w1v.y,w1v.z,w1v.w};
            unsigned long long wd[8];
            #pragma unroll
            for (int j=0;j<8;j++)
                asm("mov.b64 %0,{%1,%1};" : "=l"(wd[j]) : "f"(wv[j]));
            #pragma unroll
            for (int p=0;p<8;p++)
                #pragma unroll
                for (int j=0;j<8;j++)
                    asm("fma.rn.f32x2 %0,%1,%2,%0;"
                        : "+l"(acc[p][j]) : "l"(ap[p]), "l"(wd[j]));
        }
        __syncthreads();
    }

    float bj[8], cs[8], cq[8];
    #pragma unroll
    for (int j=0;j<8;j++){ bj[j]=b1[e0+tx*8+j]; cs[j]=0.f; cq[j]=0.f; }
    #pragma unroll
    for (int p=0;p<8;p++) {
        float v0[8], v1[8];
        #pragma unroll
        for (int j=0;j<8;j++) {
            asm("mov.b64 {%0,%1},%2;" : "=f"(v0[j]), "=f"(v1[j]) : "l"(acc[p][j]));
            v0[j]+=bj[j]; v1[j]+=bj[j];
            cs[j]+=v0[j]+v1[j]; cq[j]+=v0[j]*v0[j]+v1[j]*v1[j];
        }
        int m0r = p0 + ty*16 + 2*p;
        if (g_mv[m0r]) {
            float* xr = g_X + (size_t)m0r*DQ + e0 + tx*8;
            *(float4*)xr = *(float4*)&v0[0]; *(float4*)(xr+4) = *(float4*)&v0[4];
        }
        if (g_mv[m0r+1]) {
            float* xr = g_X + (size_t)(m0r+1)*DQ + e0 + tx*8;
            *(float4*)xr = *(float4*)&v1[0]; *(float4*)(xr+4) = *(float4*)&v1[4];
        }
    }
    float* sm = &As[0][0][0];
    #pragma unroll
    for (int j=0;j<8;j++) sm[ty*BN + tx*8+j] = cs[j];
    __syncthreads();
    if (ty==0) {
        #pragma unroll
        for (int j=0;j<8;j++){ float s=0.f; for(int r=0;r<16;r++) s+=sm[r*BN+tx*8+j];
            atomicAdd(&g_sum[e0+tx*8+j], s); }
    }
    __syncthreads();
    #pragma unroll
    for (int j=0;j<8;j++) sm[ty*BN + tx*8+j] = cq[j];
    __syncthreads();
    if (ty==0) {
        #pragma unroll
        for (int j=0;j<8;j++){ float s=0.f; for(int r=0;r<16;r++) s+=sm[r*BN+tx*8+j];
            atomicAdd(&g_sumsq[e0+tx*8+j], s); }
    }
}

__global__ void k_hsum(const float* __restrict__ gamma, const float* __restrict__ beta) {
    int t = threadIdx.x;
    float mu = g_sum[t]*(1.f/NPIX);
    float var = g_sumsq[t]*(1.f/NPIX) - mu*mu;
    float sc = gamma[t] * rsqrtf(var + 1e-5f);
    float sh = beta[t] - mu*sc;
    int ps = blockIdx.x*64;
    int b = ps >> 14;
    float a1=0.f, a0=0.f;
    #pragma unroll 4
    for (int pp=0;pp<64;pp++) {
        int p = ps+pp;
        unsigned char mv = g_mv[p];
        if (mv) {
            float h = fmaxf(fmaf(sc, g_X[(size_t)p*DQ+t], sh), 0.f);
            if (mv==1) a1 += h; else a0 += h;
        }
    }
    atomicAdd(&g_hsum[(b*2+0)*DQ+t], a1);
    atomicAdd(&g_hsum[(b*2+1)*DQ+t], a0);
}

// radix-select top-K (set semantics) — all-parallel: suffix-scan bin pick,
// rank-based tie fill, 512 threads. Then rank-select top-NS by uncertainty.
__global__ void __launch_bounds__(512,1)
k_select(const float* __restrict__ r_anc, const float* __restrict__ r_pos,
         const float* __restrict__ r_neg, const float* __restrict__ unc) {
    extern __shared__ unsigned int skey[];     // 16384 keys
    __shared__ unsigned int hist[256];
    __shared__ unsigned int sscan[256];
    __shared__ int s_remK, s_cnt, s_tie, s_B;
    __shared__ unsigned int s_prefix;
    __shared__ int outi[128]; __shared__ unsigned char outf[128];
    __shared__ int tiebuf[128];
    __shared__ float cu[128];
    const int t = threadIdx.x;
    const int pair = blockIdx.x/3, type = blockIdx.x%3;
    const int b = pair>>1, c = pair&1;
    const float* r = (type==0?r_anc:(type==1?r_pos:r_neg)) + (size_t)pair*HWQ;
    const unsigned char* mk = (type<2) ? (c==0?g_m1:g_m0) : (c==0?g_m0:g_m1);
    mk += b*HWQ;
    const int K = (type==0) ? NRQ : 2*NSQ;
    const int cnt = (type<2) ? (c==0?g_cnt1[b]:g_cnt0[b]) : (c==0?g_cnt0[b]:g_cnt1[b]);

    const float4* r4 = (const float4*)r;
    const uchar4* m4 = (const uchar4*)mk;
    for (int i=t;i<HWQ/4;i+=512) {
        float4 rv = r4[i]; uchar4 mm = m4[i];
        uint4 kv;
        kv.x = mm.x ? (__float_as_uint(rv.x)+1u) : 0u;
        kv.y = mm.y ? (__float_as_uint(rv.y)+1u) : 0u;
        kv.z = mm.z ? (__float_as_uint(rv.z)+1u) : 0u;
        kv.w = mm.w ? (__float_as_uint(rv.w)+1u) : 0u;
        *(uint4*)&skey[i*4] = kv;
    }
    if (t < K) { outi[t]=0; outf[t]=0; }
    if (t==0) { s_cnt=0; s_tie=0; s_remK=K; s_prefix=0u; s_B=-1; }
    __syncthreads();

    if (cnt > K) {
        for (int pass=0; pass<4; pass++) {
            int shift = 24 - pass*8;
            if (t < 256) hist[t] = 0u;
            __syncthreads();
            unsigned pref = s_prefix;
            for (int i=t;i<HWQ;i+=512) {
                unsigned key = skey[i];
                if (key) {
                    bool m = (pass==0) || ((key >> (shift+8)) == pref);
                    if (m) atomicAdd(&hist[(key>>shift)&255u], 1u);
                }
            }
            __syncthreads();
            // parallel suffix scan over 256 bins
            if (t < 256) sscan[t] = hist[t];
            __syncthreads();
            #pragma unroll
            for (int off=1; off<256; off<<=1) {
                unsigned v=0u;
                if (t < 256) v = sscan[t] + ((t+off<256) ? sscan[t+off] : 0u);
                __syncthreads();
                if (t < 256) sscan[t] = v;
                __syncthreads();
            }
            int rem = s_remK;
            if (t < 256 && (int)sscan[t] >= rem) atomicMax(&s_B, t);
            __syncthreads();
            if (t==0) {
                int B = s_B;
                s_remK = rem - ((B<255) ? (int)sscan[B+1] : 0);
                s_prefix = (s_prefix<<8) | (unsigned)B;
                s_B = -1;
            }
            __syncthreads();
        }
        unsigned T = s_prefix;
        for (int i=t;i<HWQ;i+=512) {
            unsigned key = skey[i];
            if (key > T) { int p = atomicAdd(&s_cnt,1); outi[p]=i; outf[p]=1; }
            else if (key == T) { int p = atomicAdd(&s_tie,1); if (p<128) tiebuf[p]=i; }
        }
        __syncthreads();
        int nt = min(s_tie, 128);
        int need = s_remK, base = s_cnt;
        if (t < nt) {
            int idx = tiebuf[t], rank = 0;
            for (int j=0;j<nt;j++) rank += (tiebuf[j] < idx);
            if (rank < need) { outi[base+rank] = idx; outf[base+rank] = 1; }
        }
        __syncthreads();
    } else {
        for (int i=t;i<HWQ;i+=512) {
            if (skey[i]) { int p=atomicAdd(&s_cnt,1); outi[p]=i; outf[p]=1; }
        }
        __syncthreads();
    }

    if (type==0) {
        if (t < NRQ) { g_anc_idx[pair*NRQ+t]=outi[t]; g_anc_val[pair*NRQ+t]=outf[t]; }
        return;
    }
    const float* ub = unc + b*HWQ;
    if (t < 128) cu[t] = outf[t] ? ub[outi[t]] : NEGF;
    __syncthreads();
    if (t < 128) {
        float u = cu[t]; int rank = 0;
        #pragma unroll 8
        for (int j=0;j<128;j++) {
            float uj = cu[j];
            rank += (uj > u) || (uj == u && j < t);
        }
        if (rank < NSQ) {
            int* oi = (type==1)?g_pos_idx:g_neg_idx;
            unsigned char* ov = (type==1)?g_pos_val:g_neg_val;
            oi[pair*NSQ+rank] = outi[t];
            ov[pair*NSQ+rank] = outf[t];
        }
    }
}

// bn+relu+w2 GEMV + L2-normalize, 8 sampled rows per block (grid 160)
__global__ void k_project(const float* __restrict__ gamma, const float* __restrict__ beta,
                          const float* __restrict__ b2) {
    __shared__ float hs[8][DQ];
    __shared__ float red[8][8];
    const int t = threadIdx.x;
    const int pair = blockIdx.x/20, r0 = (blockIdx.x%20)*8;
    const int b = pair>>1;
    float mu = g_sum[t]*(1.f/NPIX);
    float var = g_sumsq[t]*(1.f/NPIX) - mu*mu;
    float sc = gamma[t] * rsqrtf(var + 1e-5f);
    float sh = beta[t] - mu*sc;
    for (int i=0;i<8;i++) {
        int rr = r0+i, hw;
        if (rr < NRQ) hw = g_anc_idx[pair*NRQ+rr];
        else if (rr < NRQ+NSQ) hw = g_pos_idx[pair*NSQ + rr-NRQ];
        else hw = g_neg_idx[pair*NSQ + rr-NRQ-NSQ];
        size_t p = (size_t)b*HWQ + hw;
        hs[i][t] = fmaxf(fmaf(sc, g_X[p*DQ+t], sh), 0.f);
    }
    __syncthreads();
    float pr[8];
    #pragma unroll
    for (int i=0;i<8;i++) pr[i]=0.f;
    #pragma unroll 8
    for (int d=0; d<DQ; d+=4) {
        float wa = g_w2t[(d+0)*DQ+t];
        float wb = g_w2t[(d+1)*DQ+t];
        float wc = g_w2t[(d+2)*DQ+t];
        float wdd = g_w2t[(d+3)*DQ+t];
        #pragma unroll
        for (int i=0;i<8;i++) {
            float4 h = *(const float4*)&hs[i][d];
            pr[i] += h.x*wa + h.y*wb + h.z*wc + h.w*wdd;
        }
    }
    float bb = b2[t];
    #pragma unroll
    for (int i=0;i<8;i++) pr[i] += bb;
    int wid = t>>5, lane = t&31;
    #pragma unroll
    for (int i=0;i<8;i++) {
        float s = pr[i]*pr[i];
        #pragma unroll
        for (int off=16; off; off>>=1) s += __shfl_down_sync(0xffffffffu, s, off);
        if (lane==0) red[i][wid] = s;
    }
    __syncthreads();
    #pragma unroll
    for (int i=0;i<8;i++) {
        float tot=0.f;
        #pragma unroll
        for (int w=0;w<8;w++) tot += red[i][w];
        float inv = 1.f / fmaxf(sqrtf(tot), 1e-12f);
        g_q[((size_t)pair*RPP + r0 + i)*DQ + t] = pr[i]*inv;
    }
}

// local pair loss, grid 8
__global__ void k_pair() {
    extern __shared__ float sm[];
    float* qs = sm;
    float* Pt = sm + 32*QPAD;
    __shared__ float pacc[NRQ], nacc[NRQ];
    const int t = threadIdx.x, pair = blockIdx.x;
    const float* base = g_q + (size_t)pair*RPP*DQ;
    for (int i=t;i<NRQ*DQ;i+=256) qs[(i>>8)*QPAD + (i&255)] = base[i];
    if (t < NRQ) { pacc[t]=0.f; nacc[t]=0.f; }
    const int a = t>>3, s0 = (t&7)*8;
    for (int ph=0; ph<2; ph++) {
        __syncthreads();
        const float* prow = base + (size_t)(NRQ + ph*NSQ)*DQ;
        for (int i=t;i<NSQ*DQ;i+=256) Pt[(i&255)*PPAD + (i>>8)] = prow[i];
        const unsigned char* fl = (ph==0?g_pos_val:g_neg_val) + pair*NSQ;
        __syncthreads();
        float acc[8];
        #pragma unroll
        for (int j=0;j<8;j++) acc[j]=0.f;
        const float* qrow = qs + a*QPAD;
        #pragma unroll 4
        for (int d=0; d<DQ; d++) {
            float qa = qrow[d];
            const float* pp = Pt + d*PPAD + s0;
            float4 p0v = *(const float4*)pp;
            float4 p1v = *(const float4*)(pp+4);
            acc[0]+=qa*p0v.x; acc[1]+=qa*p0v.y; acc[2]+=qa*p0v.z; acc[3]+=qa*p0v.w;
            acc[4]+=qa*p1v.x; acc[5]+=qa*p1v.y; acc[6]+=qa*p1v.z; acc[7]+=qa*p1v.w;
        }
        float tot = 0.f;
        #pragma unroll
        for (int j=0;j<8;j++) if (fl[s0+j]) tot += expf(acc[j]*INVTAU);
        atomicAdd(ph ? &nacc[a] : &pacc[a], tot);
        __syncthreads();
    }
    if (t < NRQ) {
        int b = pair>>1, c = pair&1;
        int ca = c ? g_cnt0[b] : g_cnt1[b];
        int cn = c ? g_cnt1[b] : g_cnt0[b];
        int inc = (ca>=1) && (cn>=1);
        float p = pacc[t] + (inc?0.f:1.f);
        float n = nacc[t];
        float per = -logf(p/(p+n+1e-8f));
        float af = g_anc_val[pair*NRQ+t] ? 1.f : 0.f;
        float num = per*af, den = af;
        #pragma unroll
        for (int off=16; off; off>>=1) {
            num += __shfl_down_sync(0xffffffffu, num, off);
            den += __shfl_down_sync(0xffffffffu, den, off);
        }
        if (t==0 && inc) {
            atomicAdd(&g_blsum, num / fmaxf(den,1.f));
            atomicAdd(&g_incsum, 1);
        }
    }
}

// global loss + combine, 1 block
__global__ void k_final(const float* __restrict__ b2, float* __restrict__ out) {
    __shared__ float hm[8][DQ];
    __shared__ float qn[8][DQ];
    __shared__ float red[8][8];
    __shared__ float dots[24];
    const int t = threadIdx.x;
    float ind[8];
    for (int v=0; v<8; v++) {
        int b = v>>1; int cnt = (v&1) ? g_cnt0[b] : g_cnt1[b];
        hm[v][t] = g_hsum[v*DQ+t] / (float)max(cnt,1);
        ind[v] = (cnt>=1) ? 1.f : 0.f;
    }
    __syncthreads();
    float pr[8];
    #pragma unroll
    for (int v=0;v<8;v++) pr[v]=0.f;
    for (int d=0; d<DQ; d++) {
        float w = g_w2t[d*DQ+t];
        #pragma unroll
        for (int v=0;v<8;v++) pr[v] += hm[v][d]*w;
    }
    float bb = b2[t];
    #pragma unroll
    for (int v=0;v<8;v++) pr[v] += bb*ind[v];
    int wid = t>>5, lane = t&31;
    #pragma unroll
    for (int v=0;v<8;v++) {
        float s = pr[v]*pr[v];
        #pragma unroll
        for (int off=16; off; off>>=1) s += __shfl_down_sync(0xffffffffu, s, off);
        if (lane==0) red[v][wid]=s;
    }
    __syncthreads();
    #pragma unroll
    for (int v=0;v<8;v++) {
        float tot=0.f;
        #pragma unroll
        for (int w=0;w<8;w++) tot += red[v][w];
        qn[v][t] = pr[v] / fmaxf(sqrtf(tot), 1e-12f);
    }
    __syncthreads();
    for (int rd=0; rd<3; rd++) {
        int id = rd*8 + wid;
        const float *u, *vv;
        if (id < 16) { u = qn[2*(id>>2)+1]; vv = qn[2*(id&3)]; }
        else if (id < 20) { u = vv = qn[2*(id-16)]; }
        else { u = vv = qn[2*(id-20)+1]; }
        float s = 0.f;
        for (int k=lane; k<DQ; k+=32) s += u[k]*vv[k];
        #pragma unroll
        for (int off=16; off; off>>=1) s += __shfl_down_sync(0xffffffffu, s, off);
        if (lane==0) dots[id] = s;
    }
    __syncthreads();
    if (t==0) {
        float lgsum = 0.f; int vcnt = 0;
        for (int b=0;b<BQ;b++) {
            int vgb = (g_cnt1[b]>=1) && (g_cnt0[b]>=1);
            float nf=0.f, nb=0.f;
            for (int j=0;j<=b;j++) {
                int vgj = (g_cnt1[j]>=1) && (g_cnt0[j]>=1);
                if (vgj) { nf += expf(INVTAU*dots[j*4+b]); nb += expf(INVTAU*dots[b*4+j]); }
            }
            float pf = expf(INVTAU*dots[16+b]);
            float pb = expf(INVTAU*dots[20+b]);
            float lg = -logf(pf/(pf+nf+1e-8f)) - logf(pb/(pb+nb+1e-8f));
            if (vgb) { lgsum += lg; vcnt++; }
        }
        float l_global = lgsum / (float)max(vcnt,1);
        float l_local = g_blsum / (float)max(g_incsum,1);
        out[0] = l_local + 0.5f*l_global;
        out[1] = l_local;
        out[2] = l_global;
    }
}

extern "C" void kernel_launch(void* const* d_in, const int* in_sizes, int n_in,
                              void* d_out, int out_size) {
    const float* feat = (const float*)d_in[0];
    const int* labels = (const int*)d_in[1];
    const float* po = (const float*)d_in[2];
    const float* pa = (const float*)d_in[3];
    const float* unc = (const float*)d_in[4];
    const float* r_anc = (const float*)d_in[5];
    const float* r_pos = (const float*)d_in[6];
    const float* r_neg = (const float*)d_in[7];
    const float* w1 = (const float*)d_in[8];
    const float* b1 = (const float*)d_in[9];
    const float* gamma = (const float*)d_in[10];
    const float* beta = (const float*)d_in[11];
    const float* w2 = (const float*)d_in[12];
    const float* b2 = (const float*)d_in[13];
    float* out = (float*)d_out;

    cudaFuncSetAttribute(k_select, cudaFuncAttributeMaxDynamicSharedMemorySize, 65536);
    cudaFuncSetAttribute(k_pair, cudaFuncAttributeMaxDynamicSharedMemorySize, PAIR_SMEM);

    k_pre<<<328,256>>>(w1, w2, po, pa, unc, labels);
    k_gemm1<<<dim3(NPIX/BM,DQ/BN),256>>>(feat, b1);
    k_hsum<<<NPIX/64,256>>>(gamma, beta);
    k_select<<<24,512,65536>>>(r_anc, r_pos, r_neg, unc);
    k_project<<<160,256>>>(gamma, beta, b2);
    k_pair<<<8,256,PAIR_SMEM>>>();
    k_final<<<1,256>>>(b2, out);
}

// round 12
// speedup vs baseline: 1.0761x; 1.0761x over previous
#include <cuda_runtime.h>
#include <math.h>

#define BQ 4
#define DQ 256
#define HWQ 16384
#define NPIX (BQ*HWQ)
#define NRQ 32
#define NSQ 64
#define NEGF (-1e30f)
#define INVTAU 10.0f
#define NPAIR 8
#define RPP 160
#define QPAD 260
#define PPAD 72
#define PAIR_SMEM ((32*QPAD + 256*PPAD)*4)
#define BM 256
#define BN 128
#define BKK 16
#define NSEL 24
#define NGEMM 512

static __device__ float g_X[(size_t)NPIX*DQ];
static __device__ float g_w1t[DQ*DQ];
static __device__ float g_w2t[DQ*DQ];
static __device__ float g_sum[DQ], g_sumsq[DQ];
static __device__ unsigned char g_m1[NPIX], g_m0[NPIX], g_mv[NPIX];
static __device__ int g_cnt1[BQ], g_cnt0[BQ];
static __device__ float g_hsum[NPAIR*DQ];
static __device__ int g_anc_idx[NPAIR*NRQ];
static __device__ unsigned char g_anc_val[NPAIR*NRQ];
static __device__ int g_pos_idx[NPAIR*NSQ];
static __device__ unsigned char g_pos_val[NPAIR*NSQ];
static __device__ int g_neg_idx[NPAIR*NSQ];
static __device__ unsigned char g_neg_val[NPAIR*NSQ];
static __device__ float g_q[(size_t)NPAIR*RPP*DQ];
static __device__ float g_blsum;
static __device__ int g_incsum;
static __device__ int g_done;

// fused: init (blk 0..7), w1/w2 transpose (blk 8..71), masks (blk 72..327)
__global__ void k_pre(const float* __restrict__ w1, const float* __restrict__ w2,
                      const float* __restrict__ po, const float* __restrict__ pa,
                      const float* __restrict__ unc, const int* __restrict__ labels) {
    const int bid = blockIdx.x, tid = threadIdx.x;
    if (bid < 8) {
        int t = bid*256 + tid;
        if (t < DQ) { g_sum[t]=0.f; g_sumsq[t]=0.f; }
        if (t < NPAIR*DQ) g_hsum[t]=0.f;
        if (t < BQ) { g_cnt1[t]=0; g_cnt0[t]=0; }
        if (t == 0) { g_blsum=0.f; g_incsum=0; g_done=0; }
        return;
    }
    if (bid < 72) {
        __shared__ float tA[32][33], tB[32][33];
        int wb = bid - 8;
        int bx = (wb&7)*32, by = (wb>>3)*32;
        int tx = tid&31, ty = tid>>5;
        for (int r = ty; r < 32; r += 8) {
            tA[r][tx] = w1[(by+r)*DQ + bx + tx];
            tB[r][tx] = w2[(by+r)*DQ + bx + tx];
        }
        __syncthreads();
        for (int r = ty; r < 32; r += 8) {
            g_w1t[(bx+r)*DQ + by + tx] = tA[tx][r];
            g_w2t[(bx+r)*DQ + by + tx] = tB[tx][r];
        }
        return;
    }
    int g = (bid-72)*256 + tid;
    int b = g >> 14, hw = g & (HWQ-1);
    const float* pob = po + (size_t)b*2*HWQ;
    const float* pab = pa + (size_t)b*2*HWQ;
    int ao = pob[HWQ+hw] > pob[hw];
    int aa = pab[HWQ+hw] > pab[hw];
    bool valid = (ao==aa) && (unc[g] > 0.5f);
    int lab = labels[g];
    bool m1 = valid && (lab==1), m0 = valid && (lab==0);
    g_m1[g] = m1?1:0; g_m0[g] = m0?1:0;
    g_mv[g] = m1?1:(m0?2:0);
    unsigned b1m = __ballot_sync(0xffffffffu, m1);
    unsigned b0m = __ballot_sync(0xffffffffu, m0);
    if ((tid & 31) == 0) {
        atomicAdd(&g_cnt1[b], __popc(b1m));
        atomicAdd(&g_cnt0[b], __popc(b0m));
    }
}

// Fused: blocks 0..23 = radix-select (runs concurrently, hidden under GEMM);
// blocks 24..535 = GEMM tile (R8-measured winner, byte-identical core).
__global__ void __launch_bounds__(256,1)
k_gemsel(const float* __restrict__ feat, const float* __restrict__ b1,
         const float* __restrict__ r_anc, const float* __restrict__ r_pos,
         const float* __restrict__ r_neg, const float* __restrict__ unc) {
    extern __shared__ unsigned int dynsm[];     // 64KB: select keys
    const int tid = threadIdx.x;

    if (blockIdx.x < NSEL) {
        // ---------------- SELECT (256 threads) ----------------
        unsigned int* skey = dynsm;
        __shared__ unsigned int hist[256];
        __shared__ unsigned int sscan[256];
        __shared__ int s_remK, s_cnt, s_tie, s_B;
        __shared__ unsigned int s_prefix;
        __shared__ int outi[128]; __shared__ unsigned char outf[128];
        __shared__ int tiebuf[128];
        __shared__ float cu[128];
        const int t = tid;
        const int pair = blockIdx.x/3, type = blockIdx.x%3;
        const int b = pair>>1, c = pair&1;
        const float* r = (type==0?r_anc:(type==1?r_pos:r_neg)) + (size_t)pair*HWQ;
        const unsigned char* mk = (type<2) ? (c==0?g_m1:g_m0) : (c==0?g_m0:g_m1);
        mk += b*HWQ;
        const int K = (type==0) ? NRQ : 2*NSQ;
        const int cnt = (type<2) ? (c==0?g_cnt1[b]:g_cnt0[b]) : (c==0?g_cnt0[b]:g_cnt1[b]);

        const float4* r4 = (const float4*)r;
        const uchar4* m4 = (const uchar4*)mk;
        for (int i=t;i<HWQ/4;i+=256) {
            float4 rv = r4[i]; uchar4 mm = m4[i];
            uint4 kv;
            kv.x = mm.x ? (__float_as_uint(rv.x)+1u) : 0u;
            kv.y = mm.y ? (__float_as_uint(rv.y)+1u) : 0u;
            kv.z = mm.z ? (__float_as_uint(rv.z)+1u) : 0u;
            kv.w = mm.w ? (__float_as_uint(rv.w)+1u) : 0u;
            *(uint4*)&skey[i*4] = kv;
        }
        if (t < K) { outi[t]=0; outf[t]=0; }
        if (t==0) { s_cnt=0; s_tie=0; s_remK=K; s_prefix=0u; s_B=-1; }
        __syncthreads();

        if (cnt > K) {
            for (int pass=0; pass<4; pass++) {
                int shift = 24 - pass*8;
                hist[t] = 0u;
                __syncthreads();
                unsigned pref = s_prefix;
                for (int i=t;i<HWQ;i+=256) {
                    unsigned key = skey[i];
                    if (key) {
                        bool m = (pass==0) || ((key >> (shift+8)) == pref);
                        if (m) atomicAdd(&hist[(key>>shift)&255u], 1u);
                    }
                }
                __syncthreads();
                sscan[t] = hist[t];
                __syncthreads();
                #pragma unroll
                for (int off=1; off<256; off<<=1) {
                    unsigned v = sscan[t] + ((t+off<256) ? sscan[t+off] : 0u);
                    __syncthreads();
                    sscan[t] = v;
                    __syncthreads();
                }
                int rem = s_remK;
                if ((int)sscan[t] >= rem) atomicMax(&s_B, t);
                __syncthreads();
                if (t==0) {
                    int B = s_B;
                    s_remK = rem - ((B<255) ? (int)sscan[B+1] : 0);
                    s_prefix = (s_prefix<<8) | (unsigned)B;
                    s_B = -1;
                }
                __syncthreads();
            }
            unsigned T = s_prefix;
            for (int i=t;i<HWQ;i+=256) {
                unsigned key = skey[i];
                if (key > T) { int p = atomicAdd(&s_cnt,1); outi[p]=i; outf[p]=1; }
                else if (key == T) { int p = atomicAdd(&s_tie,1); if (p<128) tiebuf[p]=i; }
            }
            __syncthreads();
            int nt = min(s_tie, 128);
            int need = s_remK, base = s_cnt;
            if (t < nt) {
                int idx = tiebuf[t], rank = 0;
                for (int j=0;j<nt;j++) rank += (tiebuf[j] < idx);
                if (rank < need) { outi[base+rank] = idx; outf[base+rank] = 1; }
            }
            __syncthreads();
        } else {
            for (int i=t;i<HWQ;i+=256) {
                if (skey[i]) { int p=atomicAdd(&s_cnt,1); outi[p]=i; outf[p]=1; }
            }
            __syncthreads();
        }

        if (type==0) {
            if (t < NRQ) { g_anc_idx[pair*NRQ+t]=outi[t]; g_anc_val[pair*NRQ+t]=outf[t]; }
            return;
        }
        const float* ub = unc + b*HWQ;
        if (t < 128) cu[t] = outf[t] ? ub[outi[t]] : NEGF;
        __syncthreads();
        if (t < 128) {
            float u = cu[t]; int rank = 0;
            #pragma unroll 8
            for (int j=0;j<128;j++) {
                float uj = cu[j];
                rank += (uj > u) || (uj == u && j < t);
            }
            if (rank < NSQ) {
                int* oi = (type==1)?g_pos_idx:g_neg_idx;
                unsigned char* ov = (type==1)?g_pos_val:g_neg_val;
                oi[pair*NSQ+rank] = outi[t];
                ov[pair*NSQ+rank] = outf[t];
            }
        }
        return;
    }

    // ---------------- GEMM (R8 winner core) ----------------
    __shared__ __align__(16) float As[2][BKK][BM];
    __shared__ __align__(16) float Bs[2][BKK][BN];
    const int gbid = blockIdx.x - NSEL;
    const int tx = tid & 15, ty = tid >> 4;
    const int p0 = (gbid & 255)*BM;
    const int bq = p0 >> 14, hw0 = p0 & (HWQ-1);
    const int e0 = (gbid >> 8)*BN;
    const float* fb = feat + (size_t)bq*DQ*HWQ + hw0;
    unsigned sAb = (unsigned)__cvta_generic_to_shared(&As[0][0][0]);
    unsigned sBb = (unsigned)__cvta_generic_to_shared(&Bs[0][0][0]);

    unsigned long long acc[8][8];
    #pragma unroll
    for (int p=0;p<8;p++)
        #pragma unroll
        for (int j=0;j<8;j++) acc[p][j] = 0ull;

    auto load_tiles = [&](int buf, int k0) {
        #pragma unroll
        for (int l=0;l<4;l++) {
            int idx = tid + l*256, kk = idx>>6, m4 = (idx&63)<<2;
            unsigned d = sAb + (((buf*BKK+kk)*BM + m4)<<2);
            const float* s = fb + (size_t)(k0+kk)*HWQ + m4;
            asm volatile("cp.async.cg.shared.global [%0],[%1],16;\n"::"r"(d),"l"(s));
        }
        #pragma unroll
        for (int l=0;l<2;l++) {
            int idx = tid + l*256, kk = idx>>5, e4 = (idx&31)<<2;
            unsigned d = sBb + (((buf*BKK+kk)*BN + e4)<<2);
            const float* s = g_w1t + (k0+kk)*DQ + e0 + e4;
            asm volatile("cp.async.cg.shared.global [%0],[%1],16;\n"::"r"(d),"l"(s));
        }
        asm volatile("cp.async.commit_group;\n");
    };

    load_tiles(0, 0);
    for (int k0=0; k0<DQ; k0+=BKK) {
        int cur = (k0>>4)&1;
        if (k0+BKK < DQ) {
            load_tiles(cur^1, k0+BKK);
            asm volatile("cp.async.wait_group 1;\n");
        } else {
            asm volatile("cp.async.wait_group 0;\n");
        }
        __syncthreads();
        #pragma unroll
        for (int kk=0;kk<BKK;kk++) {
            unsigned long long ap[8];
            const unsigned long long* ar =
                (const unsigned long long*)&As[cur][kk][ty*16];
            #pragma unroll
            for (int p=0;p<8;p++) ap[p] = ar[p];
            float4 w0 = *(float4*)&Bs[cur][kk][tx*8];
            float4 w1v = *(float4*)&Bs[cur][kk][tx*8+4];
            float wv[8] = {w0.x,w0.y,w0.z,w0.w,w1v.x,w1v.y,w1v.z,w1v.w};
            unsigned long long wd[8];
            #pragma unroll
            for (int j=0;j<8;j++)
                asm("mov.b64 %0,{%1,%1};" : "=l"(wd[j]) : "f"(wv[j]));
            #pragma unroll
            for (int p=0;p<8;p++)
                #pragma unroll
                for (int j=0;j<8;j++)
                    asm("fma.rn.f32x2 %0,%1,%2,%0;"
                        : "+l"(acc[p][j]) : "l"(ap[p]), "l"(wd[j]));
        }
        __syncthreads();
    }

    float bj[8], cs[8], cq[8];
    #pragma unroll
    for (int j=0;j<8;j++){ bj[j]=b1[e0+tx*8+j]; cs[j]=0.f; cq[j]=0.f; }
    #pragma unroll
    for (int p=0;p<8;p++) {
        float v0[8], v1[8];
        #pragma unroll
        for (int j=0;j<8;j++) {
            asm("mov.b64 {%0,%1},%2;" : "=f"(v0[j]), "=f"(v1[j]) : "l"(acc[p][j]));
            v0[j]+=bj[j]; v1[j]+=bj[j];
            cs[j]+=v0[j]+v1[j]; cq[j]+=v0[j]*v0[j]+v1[j]*v1[j];
        }
        int m0r = p0 + ty*16 + 2*p;
        if (g_mv[m0r]) {
            float* xr = g_X + (size_t)m0r*DQ + e0 + tx*8;
            *(float4*)xr = *(float4*)&v0[0]; *(float4*)(xr+4) = *(float4*)&v0[4];
        }
        if (g_mv[m0r+1]) {
            float* xr = g_X + (size_t)(m0r+1)*DQ + e0 + tx*8;
            *(float4*)xr = *(float4*)&v1[0]; *(float4*)(xr+4) = *(float4*)&v1[4];
        }
    }
    float* sm = &As[0][0][0];
    #pragma unroll
    for (int j=0;j<8;j++) sm[ty*BN + tx*8+j] = cs[j];
    __syncthreads();
    if (ty==0) {
        #pragma unroll
        for (int j=0;j<8;j++){ float s=0.f; for(int r=0;r<16;r++) s+=sm[r*BN+tx*8+j];
            atomicAdd(&g_sum[e0+tx*8+j], s); }
    }
    __syncthreads();
    #pragma unroll
    for (int j=0;j<8;j++) sm[ty*BN + tx*8+j] = cq[j];
    __syncthreads();
    if (ty==0) {
        #pragma unroll
        for (int j=0;j<8;j++){ float s=0.f; for(int r=0;r<16;r++) s+=sm[r*BN+tx*8+j];
            atomicAdd(&g_sumsq[e0+tx*8+j], s); }
    }
}

__global__ void k_hsum(const float* __restrict__ gamma, const float* __restrict__ beta) {
    int t = threadIdx.x;
    float mu = g_sum[t]*(1.f/NPIX);
    float var = g_sumsq[t]*(1.f/NPIX) - mu*mu;
    float sc = gamma[t] * rsqrtf(var + 1e-5f);
    float sh = beta[t] - mu*sc;
    int ps = blockIdx.x*64;
    int b = ps >> 14;
    float a1=0.f, a0=0.f;
    #pragma unroll 4
    for (int pp=0;pp<64;pp++) {
        int p = ps+pp;
        unsigned char mv = g_mv[p];
        if (mv) {
            float h = fmaxf(fmaf(sc, g_X[(size_t)p*DQ+t], sh), 0.f);
            if (mv==1) a1 += h; else a0 += h;
        }
    }
    atomicAdd(&g_hsum[(b*2+0)*DQ+t], a1);
    atomicAdd(&g_hsum[(b*2+1)*DQ+t], a0);
}

// bn+relu+w2 GEMV + L2-normalize, 8 sampled rows per block (grid 160)
__global__ void k_project(const float* __restrict__ gamma, const float* __restrict__ beta,
                          const float* __restrict__ b2) {
    __shared__ float hs[8][DQ];
    __shared__ float red[8][8];
    const int t = threadIdx.x;
    const int pair = blockIdx.x/20, r0 = (blockIdx.x%20)*8;
    const int b = pair>>1;
    float mu = g_sum[t]*(1.f/NPIX);
    float var = g_sumsq[t]*(1.f/NPIX) - mu*mu;
    float sc = gamma[t] * rsqrtf(var + 1e-5f);
    float sh = beta[t] - mu*sc;
    for (int i=0;i<8;i++) {
        int rr = r0+i, hw;
        if (rr < NRQ) hw = g_anc_idx[pair*NRQ+rr];
        else if (rr < NRQ+NSQ) hw = g_pos_idx[pair*NSQ + rr-NRQ];
        else hw = g_neg_idx[pair*NSQ + rr-NRQ-NSQ];
        size_t p = (size_t)b*HWQ + hw;
        hs[i][t] = fmaxf(fmaf(sc, g_X[p*DQ+t], sh), 0.f);
    }
    __syncthreads();
    float pr[8];
    #pragma unroll
    for (int i=0;i<8;i++) pr[i]=0.f;
    #pragma unroll 8
    for (int d=0; d<DQ; d+=4) {
        float wa = g_w2t[(d+0)*DQ+t];
        float wb = g_w2t[(d+1)*DQ+t];
        float wc = g_w2t[(d+2)*DQ+t];
        float wdd = g_w2t[(d+3)*DQ+t];
        #pragma unroll
        for (int i=0;i<8;i++) {
            float4 h = *(const float4*)&hs[i][d];
            pr[i] += h.x*wa + h.y*wb + h.z*wc + h.w*wdd;
        }
    }
    float bb = b2[t];
    #pragma unroll
    for (int i=0;i<8;i++) pr[i] += bb;
    int wid = t>>5, lane = t&31;
    #pragma unroll
    for (int i=0;i<8;i++) {
        float s = pr[i]*pr[i];
        #pragma unroll
        for (int off=16; off; off>>=1) s += __shfl_down_sync(0xffffffffu, s, off);
        if (lane==0) red[i][wid] = s;
    }
    __syncthreads();
    #pragma unroll
    for (int i=0;i<8;i++) {
        float tot=0.f;
        #pragma unroll
        for (int w=0;w<8;w++) tot += red[i][w];
        float inv = 1.f / fmaxf(sqrtf(tot), 1e-12f);
        g_q[((size_t)pair*RPP + r0 + i)*DQ + t] = pr[i]*inv;
    }
}

// local pair loss (grid 8) + last block computes global loss & output
__global__ void k_pairfin(const float* __restrict__ b2, float* __restrict__ out) {
    extern __shared__ float sm[];
    float* qs = sm;
    float* Pt = sm + 32*QPAD;
    __shared__ float pacc[NRQ], nacc[NRQ];
    __shared__ int s_last;
    const int t = threadIdx.x, pair = blockIdx.x;
    const float* base = g_q + (size_t)pair*RPP*DQ;
    for (int i=t;i<NRQ*DQ;i+=256) qs[(i>>8)*QPAD + (i&255)] = base[i];
    if (t < NRQ) { pacc[t]=0.f; nacc[t]=0.f; }
    const int a = t>>3, s0 = (t&7)*8;
    for (int ph=0; ph<2; ph++) {
        __syncthreads();
        const float* prow = base + (size_t)(NRQ + ph*NSQ)*DQ;
        for (int i=t;i<NSQ*DQ;i+=256) Pt[(i&255)*PPAD + (i>>8)] = prow[i];
        const unsigned char* fl = (ph==0?g_pos_val:g_neg_val) + pair*NSQ;
        __syncthreads();
        float acc[8];
        #pragma unroll
        for (int j=0;j<8;j++) acc[j]=0.f;
        const float* qrow = qs + a*QPAD;
        #pragma unroll 4
        for (int d=0; d<DQ; d++) {
            float qa = qrow[d];
            const float* pp = Pt + d*PPAD + s0;
            float4 p0v = *(const float4*)pp;
            float4 p1v = *(const float4*)(pp+4);
            acc[0]+=qa*p0v.x; acc[1]+=qa*p0v.y; acc[2]+=qa*p0v.z; acc[3]+=qa*p0v.w;
            acc[4]+=qa*p1v.x; acc[5]+=qa*p1v.y; acc[6]+=qa*p1v.z; acc[7]+=qa*p1v.w;
        }
        float tot = 0.f;
        #pragma unroll
        for (int j=0;j<8;j++) if (fl[s0+j]) tot += expf(acc[j]*INVTAU);
        atomicAdd(ph ? &nacc[a] : &pacc[a], tot);
        __syncthreads();
    }
    if (t < NRQ) {
        int b = pair>>1, c = pair&1;
        int ca = c ? g_cnt0[b] : g_cnt1[b];
        int cn = c ? g_cnt1[b] : g_cnt0[b];
        int inc = (ca>=1) && (cn>=1);
        float p = pacc[t] + (inc?0.f:1.f);
        float n = nacc[t];
        float per = -logf(p/(p+n+1e-8f));
        float af = g_anc_val[pair*NRQ+t] ? 1.f : 0.f;
        float num = per*af, den = af;
        #pragma unroll
        for (int off=16; off; off>>=1) {
            num += __shfl_down_sync(0xffffffffu, num, off);
            den += __shfl_down_sync(0xffffffffu, den, off);
        }
        if (t==0 && inc) {
            atomicAdd(&g_blsum, num / fmaxf(den,1.f));
            atomicAdd(&g_incsum, 1);
        }
    }
    // ticket: last block does the global-loss epilogue
    __threadfence();
    __syncthreads();
    if (t==0) s_last = (atomicAdd(&g_done,1) == NPAIR-1);
    __syncthreads();
    if (!s_last) return;
    __threadfence();

    __shared__ float hm[8][DQ];
    __shared__ float qn[8][DQ];
    __shared__ float red[8][8];
    __shared__ float dots[24];
    float ind[8];
    for (int v=0; v<8; v++) {
        int b = v>>1; int cnt = (v&1) ? g_cnt0[b] : g_cnt1[b];
        hm[v][t] = g_hsum[v*DQ+t] / (float)max(cnt,1);
        ind[v] = (cnt>=1) ? 1.f : 0.f;
    }
    __syncthreads();
    float pr[8];
    #pragma unroll
    for (int v=0;v<8;v++) pr[v]=0.f;
    for (int d=0; d<DQ; d++) {
        float w = g_w2t[d*DQ+t];
        #pragma unroll
        for (int v=0;v<8;v++) pr[v] += hm[v][d]*w;
    }
    float bb = b2[t];
    #pragma unroll
    for (int v=0;v<8;v++) pr[v] += bb*ind[v];
    int wid = t>>5, lane = t&31;
    #pragma unroll
    for (int v=0;v<8;v++) {
        float s = pr[v]*pr[v];
        #pragma unroll
        for (int off=16; off; off>>=1) s += __shfl_down_sync(0xffffffffu, s, off);
        if (lane==0) red[v][wid]=s;
    }
    __syncthreads();
    #pragma unroll
    for (int v=0;v<8;v++) {
        float tot=0.f;
        #pragma unroll
        for (int w=0;w<8;w++) tot += red[v][w];
        qn[v][t] = pr[v] / fmaxf(sqrtf(tot), 1e-12f);
    }
    __syncthreads();
    for (int rd=0; rd<3; rd++) {
        int id = rd*8 + wid;
        const float *u, *vv;
        if (id < 16) { u = qn[2*(id>>2)+1]; vv = qn[2*(id&3)]; }
        else if (id < 20) { u = vv = qn[2*(id-16)]; }
        else { u = vv = qn[2*(id-20)+1]; }
        float s = 0.f;
        for (int k=lane; k<DQ; k+=32) s += u[k]*vv[k];
        #pragma unroll
        for (int off=16; off; off>>=1) s += __shfl_down_sync(0xffffffffu, s, off);
        if (lane==0) dots[id] = s;
    }
    __syncthreads();
    if (t==0) {
        float lgsum = 0.f; int vcnt = 0;
        for (int b=0;b<BQ;b++) {
            int vgb = (g_cnt1[b]>=1) && (g_cnt0[b]>=1);
            float nf=0.f, nb=0.f;
            for (int j=0;j<=b;j++) {
                int vgj = (g_cnt1[j]>=1) && (g_cnt0[j]>=1);
                if (vgj) { nf += expf(INVTAU*dots[j*4+b]); nb += expf(INVTAU*dots[b*4+j]); }
            }
            float pf = expf(INVTAU*dots[16+b]);
            float pb = expf(INVTAU*dots[20+b]);
            float lg = -logf(pf/(pf+nf+1e-8f)) - logf(pb/(pb+nb+1e-8f));
            if (vgb) { lgsum += lg; vcnt++; }
        }
        float l_global = lgsum / (float)max(vcnt,1);
        float l_local = g_blsum / (float)max(g_incsum,1);
        out[0] = l_local + 0.5f*l_global;
        out[1] = l_local;
        out[2] = l_global;
    }
}

extern "C" void kernel_launch(void* const* d_in, const int* in_sizes, int n_in,
                              void* d_out, int out_size) {
    const float* feat = (const float*)d_in[0];
    const int* labels = (const int*)d_in[1];
    const float* po = (const float*)d_in[2];
    const float* pa = (const float*)d_in[3];
    const float* unc = (const float*)d_in[4];
    const float* r_anc = (const float*)d_in[5];
    const float* r_pos = (const float*)d_in[6];
    const float* r_neg = (const float*)d_in[7];
    const float* w1 = (const float*)d_in[8];
    const float* b1 = (const float*)d_in[9];
    const float* gamma = (const float*)d_in[10];
    const float* beta = (const float*)d_in[11];
    const float* w2 = (const float*)d_in[12];
    const float* b2 = (const float*)d_in[13];
    float* out = (float*)d_out;

    cudaFuncSetAttribute(k_gemsel, cudaFuncAttributeMaxDynamicSharedMemorySize, 65536);
    cudaFuncSetAttribute(k_pairfin, cudaFuncAttributeMaxDynamicSharedMemorySize, PAIR_SMEM);

    k_pre<<<328,256>>>(w1, w2, po, pa, unc, labels);
    k_gemsel<<<NSEL+NGEMM,256,65536>>>(feat, b1, r_anc, r_pos, r_neg, unc);
    k_hsum<<<NPIX/64,256>>>(gamma, beta);
    k_project<<<160,256>>>(gamma, beta, b2);
    k_pairfin<<<8,256,PAIR_SMEM>>>(b2, out);
}

// round 15
// speedup vs baseline: 1.1555x; 1.0738x over previous
#include <cuda_runtime.h>
#include <math.h>

#define BQ 4
#define DQ 256
#define HWQ 16384
#define NPIX (BQ*HWQ)
#define NRQ 32
#define NSQ 64
#define NEGF (-1e30f)
#define INVTAU 10.0f
#define NPAIR 8
#define RPP 160
#define QPAD 260
#define PPAD 72
#define PAIR_SMEM ((32*QPAD + 256*PPAD)*4)
#define BM 256
#define BN 128
#define BKK 16
#define NSEL 24
#define NGEMM 512
#define NPROJ 160

static __device__ float g_X[(size_t)NPIX*DQ];
static __device__ float g_w1t[DQ*DQ];
static __device__ float g_w2t[DQ*DQ];
static __device__ float g_sum[DQ], g_sumsq[DQ];
static __device__ unsigned char g_m1[NPIX], g_m0[NPIX], g_mv[NPIX];
static __device__ int g_cnt1[BQ], g_cnt0[BQ];
static __device__ float g_hsum[NPAIR*DQ];
static __device__ int g_anc_idx[NPAIR*NRQ];
static __device__ unsigned char g_anc_val[NPAIR*NRQ];
static __device__ int g_pos_idx[NPAIR*NSQ];
static __device__ unsigned char g_pos_val[NPAIR*NSQ];
static __device__ int g_neg_idx[NPAIR*NSQ];
static __device__ unsigned char g_neg_val[NPAIR*NSQ];
static __device__ float g_q[(size_t)NPAIR*RPP*DQ];
static __device__ float g_blsum;
static __device__ int g_incsum;
static __device__ int g_done;

// fused: init (blk 0..7), w1/w2 transpose (blk 8..71), masks (blk 72..327)
__global__ void k_pre(const float* __restrict__ w1, const float* __restrict__ w2,
                      const float* __restrict__ po, const float* __restrict__ pa,
                      const float* __restrict__ unc, const int* __restrict__ labels) {
    const int bid = blockIdx.x, tid = threadIdx.x;
    if (bid < 8) {
        int t = bid*256 + tid;
        if (t < DQ) { g_sum[t]=0.f; g_sumsq[t]=0.f; }
        if (t < NPAIR*DQ) g_hsum[t]=0.f;
        if (t < BQ) { g_cnt1[t]=0; g_cnt0[t]=0; }
        if (t == 0) { g_blsum=0.f; g_incsum=0; g_done=0; }
        return;
    }
    if (bid < 72) {
        __shared__ float tA[32][33], tB[32][33];
        int wb = bid - 8;
        int bx = (wb&7)*32, by = (wb>>3)*32;
        int tx = tid&31, ty = tid>>5;
        for (int r = ty; r < 32; r += 8) {
            tA[r][tx] = w1[(by+r)*DQ + bx + tx];
            tB[r][tx] = w2[(by+r)*DQ + bx + tx];
        }
        __syncthreads();
        for (int r = ty; r < 32; r += 8) {
            g_w1t[(bx+r)*DQ + by + tx] = tA[tx][r];
            g_w2t[(bx+r)*DQ + by + tx] = tB[tx][r];
        }
        return;
    }
    int g = (bid-72)*256 + tid;
    int b = g >> 14, hw = g & (HWQ-1);
    const float* pob = po + (size_t)b*2*HWQ;
    const float* pab = pa + (size_t)b*2*HWQ;
    int ao = pob[HWQ+hw] > pob[hw];
    int aa = pab[HWQ+hw] > pab[hw];
    bool valid = (ao==aa) && (unc[g] > 0.5f);
    int lab = labels[g];
    bool m1 = valid && (lab==1), m0 = valid && (lab==0);
    g_m1[g] = m1?1:0; g_m0[g] = m0?1:0;
    g_mv[g] = m1?1:(m0?2:0);
    unsigned b1m = __ballot_sync(0xffffffffu, m1);
    unsigned b0m = __ballot_sync(0xffffffffu, m0);
    if ((tid & 31) == 0) {
        atomicAdd(&g_cnt1[b], __popc(b1m));
        atomicAdd(&g_cnt0[b], __popc(b0m));
    }
}

// Fused: blocks 0..23 = radix-select (hidden under GEMM);
// blocks 24..535 = GEMM tile (R8-measured winner core).
__global__ void __launch_bounds__(256,1)
k_gemsel(const float* __restrict__ feat, const float* __restrict__ b1,
         const float* __restrict__ r_anc, const float* __restrict__ r_pos,
         const float* __restrict__ r_neg, const float* __restrict__ unc) {
    extern __shared__ unsigned int dynsm[];
    const int tid = threadIdx.x;

    if (blockIdx.x < NSEL) {
        unsigned int* skey = dynsm;
        __shared__ unsigned int hist[256];
        __shared__ unsigned int sscan[256];
        __shared__ int s_remK, s_cnt, s_tie, s_B;
        __shared__ unsigned int s_prefix;
        __shared__ int outi[128]; __shared__ unsigned char outf[128];
        __shared__ int tiebuf[128];
        __shared__ float cu[128];
        const int t = tid;
        const int pair = blockIdx.x/3, type = blockIdx.x%3;
        const int b = pair>>1, c = pair&1;
        const float* r = (type==0?r_anc:(type==1?r_pos:r_neg)) + (size_t)pair*HWQ;
        const unsigned char* mk = (type<2) ? (c==0?g_m1:g_m0) : (c==0?g_m0:g_m1);
        mk += b*HWQ;
        const int K = (type==0) ? NRQ : 2*NSQ;
        const int cnt = (type<2) ? (c==0?g_cnt1[b]:g_cnt0[b]) : (c==0?g_cnt0[b]:g_cnt1[b]);

        const float4* r4 = (const float4*)r;
        const uchar4* m4 = (const uchar4*)mk;
        for (int i=t;i<HWQ/4;i+=256) {
            float4 rv = r4[i]; uchar4 mm = m4[i];
            uint4 kv;
            kv.x = mm.x ? (__float_as_uint(rv.x)+1u) : 0u;
            kv.y = mm.y ? (__float_as_uint(rv.y)+1u) : 0u;
            kv.z = mm.z ? (__float_as_uint(rv.z)+1u) : 0u;
            kv.w = mm.w ? (__float_as_uint(rv.w)+1u) : 0u;
            *(uint4*)&skey[i*4] = kv;
        }
        if (t < K) { outi[t]=0; outf[t]=0; }
        if (t==0) { s_cnt=0; s_tie=0; s_remK=K; s_prefix=0u; s_B=-1; }
        __syncthreads();

        if (cnt > K) {
            for (int pass=0; pass<4; pass++) {
                int shift = 24 - pass*8;
                hist[t] = 0u;
                __syncthreads();
                unsigned pref = s_prefix;
                for (int i=t;i<HWQ;i+=256) {
                    unsigned key = skey[i];
                    if (key) {
                        bool m = (pass==0) || ((key >> (shift+8)) == pref);
                        if (m) atomicAdd(&hist[(key>>shift)&255u], 1u);
                    }
                }
                __syncthreads();
                sscan[t] = hist[t];
                __syncthreads();
                #pragma unroll
                for (int off=1; off<256; off<<=1) {
                    unsigned v = sscan[t] + ((t+off<256) ? sscan[t+off] : 0u);
                    __syncthreads();
                    sscan[t] = v;
                    __syncthreads();
                }
                int rem = s_remK;
                if ((int)sscan[t] >= rem) atomicMax(&s_B, t);
                __syncthreads();
                if (t==0) {
                    int B = s_B;
                    s_remK = rem - ((B<255) ? (int)sscan[B+1] : 0);
                    s_prefix = (s_prefix<<8) | (unsigned)B;
                    s_B = -1;
                }
                __syncthreads();
            }
            unsigned T = s_prefix;
            for (int i=t;i<HWQ;i+=256) {
                unsigned key = skey[i];
                if (key > T) { int p = atomicAdd(&s_cnt,1); outi[p]=i; outf[p]=1; }
                else if (key == T) { int p = atomicAdd(&s_tie,1); if (p<128) tiebuf[p]=i; }
            }
            __syncthreads();
            int nt = min(s_tie, 128);
            int need = s_remK, base = s_cnt;
            if (t < nt) {
                int idx = tiebuf[t], rank = 0;
                for (int j=0;j<nt;j++) rank += (tiebuf[j] < idx);
                if (rank < need) { outi[base+rank] = idx; outf[base+rank] = 1; }
            }
            __syncthreads();
        } else {
            for (int i=t;i<HWQ;i+=256) {
                if (skey[i]) { int p=atomicAdd(&s_cnt,1); outi[p]=i; outf[p]=1; }
            }
            __syncthreads();
        }

        if (type==0) {
            if (t < NRQ) { g_anc_idx[pair*NRQ+t]=outi[t]; g_anc_val[pair*NRQ+t]=outf[t]; }
            return;
        }
        const float* ub = unc + b*HWQ;
        if (t < 128) cu[t] = outf[t] ? ub[outi[t]] : NEGF;
        __syncthreads();
        if (t < 128) {
            float u = cu[t]; int rank = 0;
            #pragma unroll 8
            for (int j=0;j<128;j++) {
                float uj = cu[j];
                rank += (uj > u) || (uj == u && j < t);
            }
            if (rank < NSQ) {
                int* oi = (type==1)?g_pos_idx:g_neg_idx;
                unsigned char* ov = (type==1)?g_pos_val:g_neg_val;
                oi[pair*NSQ+rank] = outi[t];
                ov[pair*NSQ+rank] = outf[t];
            }
        }
        return;
    }

    // ---------------- GEMM ----------------
    __shared__ __align__(16) float As[2][BKK][BM];
    __shared__ __align__(16) float Bs[2][BKK][BN];
    const int gbid = blockIdx.x - NSEL;
    const int tx = tid & 15, ty = tid >> 4;
    const int p0 = (gbid & 255)*BM;
    const int bq = p0 >> 14, hw0 = p0 & (HWQ-1);
    const int e0 = (gbid >> 8)*BN;
    const float* fb = feat + (size_t)bq*DQ*HWQ + hw0;
    unsigned sAb = (unsigned)__cvta_generic_to_shared(&As[0][0][0]);
    unsigned sBb = (unsigned)__cvta_generic_to_shared(&Bs[0][0][0]);

    unsigned long long acc[8][8];
    #pragma unroll
    for (int p=0;p<8;p++)
        #pragma unroll
        for (int j=0;j<8;j++) acc[p][j] = 0ull;

    auto load_tiles = [&](int buf, int k0) {
        #pragma unroll
        for (int l=0;l<4;l++) {
            int idx = tid + l*256, kk = idx>>6, m4 = (idx&63)<<2;
            unsigned d = sAb + (((buf*BKK+kk)*BM + m4)<<2);
            const float* s = fb + (size_t)(k0+kk)*HWQ + m4;
            asm volatile("cp.async.cg.shared.global [%0],[%1],16;\n"::"r"(d),"l"(s));
        }
        #pragma unroll
        for (int l=0;l<2;l++) {
            int idx = tid + l*256, kk = idx>>5, e4 = (idx&31)<<2;
            unsigned d = sBb + (((buf*BKK+kk)*BN + e4)<<2);
            const float* s = g_w1t + (k0+kk)*DQ + e0 + e4;
            asm volatile("cp.async.cg.shared.global [%0],[%1],16;\n"::"r"(d),"l"(s));
        }
        asm volatile("cp.async.commit_group;\n");
    };

    load_tiles(0, 0);
    for (int k0=0; k0<DQ; k0+=BKK) {
        int cur = (k0>>4)&1;
        if (k0+BKK < DQ) {
            load_tiles(cur^1, k0+BKK);
            asm volatile("cp.async.wait_group 1;\n");
        } else {
            asm volatile("cp.async.wait_group 0;\n");
        }
        __syncthreads();
        #pragma unroll
        for (int kk=0;kk<BKK;kk++) {
            unsigned long long ap[8];
            const unsigned long long* ar =
                (const unsigned long long*)&As[cur][kk][ty*16];
            #pragma unroll
            for (int p=0;p<8;p++) ap[p] = ar[p];
            float4 w0 = *(float4*)&Bs[cur][kk][tx*8];
            float4 w1v = *(float4*)&Bs[cur][kk][tx*8+4];
            float wv[8] = {w0.x,w0.y,w0.z,w0.w,w1v.x,w1v.y,w1v.z,w1v.w};
            unsigned long long wd[8];
            #pragma unroll
            for (int j=0;j<8;j++)
                asm("mov.b64 %0,{%1,%1};" : "=l"(wd[j]) : "f"(wv[j]));
            #pragma unroll
            for (int p=0;p<8;p++)
                #pragma unroll
                for (int j=0;j<8;j++)
                    asm("fma.rn.f32x2 %0,%1,%2,%0;"
                        : "+l"(acc[p][j]) : "l"(ap[p]), "l"(wd[j]));
        }
        __syncthreads();
    }

    float bj[8], cs[8], cq[8];
    #pragma unroll
    for (int j=0;j<8;j++){ bj[j]=b1[e0+tx*8+j]; cs[j]=0.f; cq[j]=0.f; }
    #pragma unroll
    for (int p=0;p<8;p++) {
        float v0[8], v1[8];
        #pragma unroll
        for (int j=0;j<8;j++) {
            asm("mov.b64 {%0,%1},%2;" : "=f"(v0[j]), "=f"(v1[j]) : "l"(acc[p][j]));
            v0[j]+=bj[j]; v1[j]+=bj[j];
            cs[j]+=v0[j]+v1[j]; cq[j]+=v0[j]*v0[j]+v1[j]*v1[j];
        }
        int m0r = p0 + ty*16 + 2*p;
        if (g_mv[m0r]) {
            float* xr = g_X + (size_t)m0r*DQ + e0 + tx*8;
            *(float4*)xr = *(float4*)&v0[0]; *(float4*)(xr+4) = *(float4*)&v0[4];
        }
        if (g_mv[m0r+1]) {
            float* xr = g_X + (size_t)(m0r+1)*DQ + e0 + tx*8;
            *(float4*)xr = *(float4*)&v1[0]; *(float4*)(xr+4) = *(float4*)&v1[4];
        }
    }
    float* sm = &As[0][0][0];
    #pragma unroll
    for (int j=0;j<8;j++) sm[ty*BN + tx*8+j] = cs[j];
    __syncthreads();
    if (ty==0) {
        #pragma unroll
        for (int j=0;j<8;j++){ float s=0.f; for(int r=0;r<16;r++) s+=sm[r*BN+tx*8+j];
            atomicAdd(&g_sum[e0+tx*8+j], s); }
    }
    __syncthreads();
    #pragma unroll
    for (int j=0;j<8;j++) sm[ty*BN + tx*8+j] = cq[j];
    __syncthreads();
    if (ty==0) {
        #pragma unroll
        for (int j=0;j<8;j++){ float s=0.f; for(int r=0;r<16;r++) s+=sm[r*BN+tx*8+j];
            atomicAdd(&g_sumsq[e0+tx*8+j], s); }
    }
}

// Fused post: blocks 0..159 = project (16-deep w prefetch), 160..1183 = hsum.
__global__ void __launch_bounds__(256,1)
k_post(const float* __restrict__ gamma, const float* __restrict__ beta,
       const float* __restrict__ b2) {
    const int t = threadIdx.x;
    float mu = g_sum[t]*(1.f/NPIX);
    float var = g_sumsq[t]*(1.f/NPIX) - mu*mu;
    float sc = gamma[t] * rsqrtf(var + 1e-5f);
    float sh = beta[t] - mu*sc;

    if (blockIdx.x >= NPROJ) {
        // ---------------- hsum ----------------
        int ps = (blockIdx.x - NPROJ)*64;
        int b = ps >> 14;
        float a1=0.f, a0=0.f;
        #pragma unroll 4
        for (int pp=0;pp<64;pp++) {
            int p = ps+pp;
            unsigned char mv = g_mv[p];
            if (mv) {
                float h = fmaxf(fmaf(sc, g_X[(size_t)p*DQ+t], sh), 0.f);
                if (mv==1) a1 += h; else a0 += h;
            }
        }
        atomicAdd(&g_hsum[(b*2+0)*DQ+t], a1);
        atomicAdd(&g_hsum[(b*2+1)*DQ+t], a0);
        return;
    }

    // ---------------- project ----------------
    __shared__ float hs[8][DQ];
    __shared__ float red[8][8];
    const int pair = blockIdx.x/20, r0 = (blockIdx.x%20)*8;
    const int b = pair>>1;
    for (int i=0;i<8;i++) {
        int rr = r0+i, hw;
        if (rr < NRQ) hw = g_anc_idx[pair*NRQ+rr];
        else if (rr < NRQ+NSQ) hw = g_pos_idx[pair*NSQ + rr-NRQ];
        else hw = g_neg_idx[pair*NSQ + rr-NRQ-NSQ];
        size_t p = (size_t)b*HWQ + hw;
        hs[i][t] = fmaxf(fmaf(sc, g_X[p*DQ+t], sh), 0.f);
    }
    __syncthreads();
    float pr[8];
    #pragma unroll
    for (int i=0;i<8;i++) pr[i]=0.f;
    const float* wp = g_w2t + t;
    float wn[16];
    #pragma unroll
    for (int q=0;q<16;q++) wn[q] = wp[q*DQ];
    for (int d0=0; d0<DQ; d0+=16) {
        float wc[16];
        #pragma unroll
        for (int q=0;q<16;q++) wc[q] = wn[q];
        if (d0+16 < DQ) {
            #pragma unroll
            for (int q=0;q<16;q++) wn[q] = wp[(d0+16+q)*DQ];
        }
        #pragma unroll
        for (int dd=0; dd<16; dd+=4) {
            #pragma unroll
            for (int i=0;i<8;i++) {
                float4 h = *(const float4*)&hs[i][d0+dd];
                pr[i] += h.x*wc[dd] + h.y*wc[dd+1] + h.z*wc[dd+2] + h.w*wc[dd+3];
            }
        }
    }
    float bb = b2[t];
    #pragma unroll
    for (int i=0;i<8;i++) pr[i] += bb;
    int wid = t>>5, lane = t&31;
    #pragma unroll
    for (int i=0;i<8;i++) {
        float s = pr[i]*pr[i];
        #pragma unroll
        for (int off=16; off; off>>=1) s += __shfl_down_sync(0xffffffffu, s, off);
        if (lane==0) red[i][wid] = s;
    }
    __syncthreads();
    #pragma unroll
    for (int i=0;i<8;i++) {
        float tot=0.f;
        #pragma unroll
        for (int w=0;w<8;w++) tot += red[i][w];
        float inv = 1.f / fmaxf(sqrtf(tot), 1e-12f);
        g_q[((size_t)pair*RPP + r0 + i)*DQ + t] = pr[i]*inv;
    }
}

// local pair loss (grid 8) + last block computes global loss & output
__global__ void k_pairfin(const float* __restrict__ b2, float* __restrict__ out) {
    extern __shared__ float sm[];
    float* qs = sm;
    float* Pt = sm + 32*QPAD;
    __shared__ float pacc[NRQ], nacc[NRQ];
    __shared__ int s_last;
    const int t = threadIdx.x, pair = blockIdx.x;
    const float* base = g_q + (size_t)pair*RPP*DQ;
    for (int i=t;i<NRQ*DQ;i+=256) qs[(i>>8)*QPAD + (i&255)] = base[i];
    if (t < NRQ) { pacc[t]=0.f; nacc[t]=0.f; }
    const int a = t>>3, s0 = (t&7)*8;
    for (int ph=0; ph<2; ph++) {
        __syncthreads();
        const float* prow = base + (size_t)(NRQ + ph*NSQ)*DQ;
        for (int i=t;i<NSQ*DQ;i+=256) Pt[(i&255)*PPAD + (i>>8)] = prow[i];
        const unsigned char* fl = (ph==0?g_pos_val:g_neg_val) + pair*NSQ;
        __syncthreads();
        float acc[8];
        #pragma unroll
        for (int j=0;j<8;j++) acc[j]=0.f;
        const float* qrow = qs + a*QPAD;
        #pragma unroll 4
        for (int d=0; d<DQ; d++) {
            float qa = qrow[d];
            const float* pp = Pt + d*PPAD + s0;
            float4 p0v = *(const float4*)pp;
            float4 p1v = *(const float4*)(pp+4);
            acc[0]+=qa*p0v.x; acc[1]+=qa*p0v.y; acc[2]+=qa*p0v.z; acc[3]+=qa*p0v.w;
            acc[4]+=qa*p1v.x; acc[5]+=qa*p1v.y; acc[6]+=qa*p1v.z; acc[7]+=qa*p1v.w;
        }
        float tot = 0.f;
        #pragma unroll
        for (int j=0;j<8;j++) if (fl[s0+j]) tot += expf(acc[j]*INVTAU);
        atomicAdd(ph ? &nacc[a] : &pacc[a], tot);
        __syncthreads();
    }
    if (t < NRQ) {
        int b = pair>>1, c = pair&1;
        int ca = c ? g_cnt0[b] : g_cnt1[b];
        int cn = c ? g_cnt1[b] : g_cnt0[b];
        int inc = (ca>=1) && (cn>=1);
        float p = pacc[t] + (inc?0.f:1.f);
        float n = nacc[t];
        float per = -logf(p/(p+n+1e-8f));
        float af = g_anc_val[pair*NRQ+t] ? 1.f : 0.f;
        float num = per*af, den = af;
        #pragma unroll
        for (int off=16; off; off>>=1) {
            num += __shfl_down_sync(0xffffffffu, num, off);
            den += __shfl_down_sync(0xffffffffu, den, off);
        }
        if (t==0 && inc) {
            atomicAdd(&g_blsum, num / fmaxf(den,1.f));
            atomicAdd(&g_incsum, 1);
        }
    }
    __threadfence();
    __syncthreads();
    if (t==0) s_last = (atomicAdd(&g_done,1) == NPAIR-1);
    __syncthreads();
    if (!s_last) return;
    __threadfence();

    __shared__ float hm[8][DQ];
    __shared__ float qn[8][DQ];
    __shared__ float red[8][8];
    __shared__ float dots[24];
    float ind[8];
    for (int v=0; v<8; v++) {
        int b = v>>1; int cnt = (v&1) ? g_cnt0[b] : g_cnt1[b];
        hm[v][t] = g_hsum[v*DQ+t] / (float)max(cnt,1);
        ind[v] = (cnt>=1) ? 1.f : 0.f;
    }
    __syncthreads();
    float pr[8];
    #pragma unroll
    for (int v=0;v<8;v++) pr[v]=0.f;
    for (int d=0; d<DQ; d++) {
        float w = g_w2t[d*DQ+t];
        #pragma unroll
        for (int v=0;v<8;v++) pr[v] += hm[v][d]*w;
    }
    float bb = b2[t];
    #pragma unroll
    for (int v=0;v<8;v++) pr[v] += bb*ind[v];
    int wid = t>>5, lane = t&31;
    #pragma unroll
    for (int v=0;v<8;v++) {
        float s = pr[v]*pr[v];
        #pragma unroll
        for (int off=16; off; off>>=1) s += __shfl_down_sync(0xffffffffu, s, off);
        if (lane==0) red[v][wid]=s;
    }
    __syncthreads();
    #pragma unroll
    for (int v=0;v<8;v++) {
        float tot=0.f;
        #pragma unroll
        for (int w=0;w<8;w++) tot += red[v][w];
        qn[v][t] = pr[v] / fmaxf(sqrtf(tot), 1e-12f);
    }
    __syncthreads();
    for (int rd=0; rd<3; rd++) {
        int id = rd*8 + wid;
        const float *u, *vv;
        if (id < 16) { u = qn[2*(id>>2)+1]; vv = qn[2*(id&3)]; }
        else if (id < 20) { u = vv = qn[2*(id-16)]; }
        else { u = vv = qn[2*(id-20)+1]; }
        float s = 0.f;
        for (int k=lane; k<DQ; k+=32) s += u[k]*vv[k];
        #pragma unroll
        for (int off=16; off; off>>=1) s += __shfl_down_sync(0xffffffffu, s, off);
        if (lane==0) dots[id] = s;
    }
    __syncthreads();
    if (t==0) {
        float lgsum = 0.f; int vcnt = 0;
        for (int b=0;b<BQ;b++) {
            int vgb = (g_cnt1[b]>=1) && (g_cnt0[b]>=1);
            float nf=0.f, nb=0.f;
            for (int j=0;j<=b;j++) {
                int vgj = (g_cnt1[j]>=1) && (g_cnt0[j]>=1);
                if (vgj) { nf += expf(INVTAU*dots[j*4+b]); nb += expf(INVTAU*dots[b*4+j]); }
            }
            float pf = expf(INVTAU*dots[16+b]);
            float pb = expf(INVTAU*dots[20+b]);
            float lg = -logf(pf/(pf+nf+1e-8f)) - logf(pb/(pb+nb+1e-8f));
            if (vgb) { lgsum += lg; vcnt++; }
        }
        float l_global = lgsum / (float)max(vcnt,1);
        float l_local = g_blsum / (float)max(g_incsum,1);
        out[0] = l_local + 0.5f*l_global;
        out[1] = l_local;
        out[2] = l_global;
    }
}

extern "C" void kernel_launch(void* const* d_in, const int* in_sizes, int n_in,
                              void* d_out, int out_size) {
    const float* feat = (const float*)d_in[0];
    const int* labels = (const int*)d_in[1];
    const float* po = (const float*)d_in[2];
    const float* pa = (const float*)d_in[3];
    const float* unc = (const float*)d_in[4];
    const float* r_anc = (const float*)d_in[5];
    const float* r_pos = (const float*)d_in[6];
    const float* r_neg = (const float*)d_in[7];
    const float* w1 = (const float*)d_in[8];
    const float* b1 = (const float*)d_in[9];
    const float* gamma = (const float*)d_in[10];
    const float* beta = (const float*)d_in[11];
    const float* w2 = (const float*)d_in[12];
    const float* b2 = (const float*)d_in[13];
    float* out = (float*)d_out;

    cudaFuncSetAttribute(k_gemsel, cudaFuncAttributeMaxDynamicSharedMemorySize, 65536);
    cudaFuncSetAttribute(k_pairfin, cudaFuncAttributeMaxDynamicSharedMemorySize, PAIR_SMEM);

    k_pre<<<328,256>>>(w1, w2, po, pa, unc, labels);
    k_gemsel<<<NSEL+NGEMM,256,65536>>>(feat, b1, r_anc, r_pos, r_neg, unc);
    k_post<<<NPROJ + NPIX/64,256>>>(gamma, beta, b2);
    k_pairfin<<<8,256,PAIR_SMEM>>>(b2, out);
}